// round 1
// baseline (speedup 1.0000x reference)
#include <cuda_runtime.h>

#define NB 64
#define NC 2
#define LSIG 131072
#define K 4
#define NCH (NB*NC)
#define THREADS 1024
#define CHUNK (LSIG/THREADS)   /* 128 */
#define LEVELS 10              /* log2(THREADS) */

struct Coef { float b0[K], b1[K], b2[K], a1[K], a2[K]; };

__device__ __forceinline__ float cascade_step(float u, float s1[K], float s2[K], const Coef& cf) {
#pragma unroll
    for (int k = 0; k < K; ++k) {
        float y = fmaf(cf.b0[k], u, s1[k]);
        s1[k] = fmaf(cf.b1[k], u, fmaf(-cf.a1[k], y, s2[k]));
        s2[k] = fmaf(cf.b2[k], u, -cf.a2[k] * y);
        u = y;
    }
    return u;
}

__global__ void __launch_bounds__(THREADS, 1)
iir_cascade_kernel(const float* __restrict__ x,
                   const float* __restrict__ Bs,
                   const float* __restrict__ As,
                   float* __restrict__ yout)
{
    __shared__ float S[THREADS][8];          // per-chunk states (scan array)
    __shared__ float Mats[LEVELS][8][8];     // A^(CHUNK * 2^l)
    __shared__ float P[8][8];                // running power of A

    const int ch  = blockIdx.x;
    const int tid = threadIdx.x;

    // ---- load + normalize coefficients (a0 division like reference) ----
    Coef cf;
    {
        const float* bs = Bs + (size_t)ch * K * 3;
        const float* as = As + (size_t)ch * K * 3;
#pragma unroll
        for (int k = 0; k < K; ++k) {
            float inv = 1.0f / as[k * 3 + 0];
            cf.b0[k] = bs[k * 3 + 0] * inv;
            cf.b1[k] = bs[k * 3 + 1] * inv;
            cf.b2[k] = bs[k * 3 + 2] * inv;
            cf.a1[k] = as[k * 3 + 1] * inv;
            cf.a2[k] = as[k * 3 + 2] * inv;
        }
    }

    const float4* __restrict__ xin =
        reinterpret_cast<const float4*>(x + (size_t)ch * LSIG + (size_t)tid * CHUNK);

    // ---- Pass A: zero-init run over this thread's chunk -> final state u_p ----
    float s1[K] = {0.f, 0.f, 0.f, 0.f};
    float s2[K] = {0.f, 0.f, 0.f, 0.f};
#pragma unroll 1
    for (int i = 0; i < CHUNK / 4; ++i) {
        float4 v = xin[i];
        cascade_step(v.x, s1, s2, cf);
        cascade_step(v.y, s1, s2, cf);
        cascade_step(v.z, s1, s2, cf);
        cascade_step(v.w, s1, s2, cf);
    }
    float sc[8];
#pragma unroll
    for (int k = 0; k < K; ++k) { sc[2 * k] = s1[k]; sc[2 * k + 1] = s2[k]; }
#pragma unroll
    for (int i = 0; i < 8; ++i) S[tid][i] = sc[i];

    // ---- Build state matrix A: column i = one step with x=0, s=e_i ----
    if (tid < 8) {
        float t1[K], t2[K];
#pragma unroll
        for (int k = 0; k < K; ++k) {
            t1[k] = (2 * k     == tid) ? 1.f : 0.f;
            t2[k] = (2 * k + 1 == tid) ? 1.f : 0.f;
        }
        cascade_step(0.f, t1, t2, cf);
#pragma unroll
        for (int k = 0; k < K; ++k) {
            P[2 * k][tid]     = t1[k];
            P[2 * k + 1][tid] = t2[k];
        }
    }
    __syncthreads();

    // ---- Repeated squaring: after it-th squaring P = A^(2^it).
    //      Store Mats[it-7] = A^(2^(it)) for it = 7..16  (A^128 .. A^65536) ----
    for (int it = 1; it <= 16; ++it) {
        float val = 0.f;
        int r = tid >> 3, c = tid & 7;
        if (tid < 64) {
#pragma unroll
            for (int kk = 0; kk < 8; ++kk) val = fmaf(P[r][kk], P[kk][c], val);
        }
        __syncthreads();
        if (tid < 64) {
            P[r][c] = val;
            if (it >= 7) Mats[it - 7][r][c] = val;
        }
        __syncthreads();
    }

    // ---- Kogge-Stone affine scan: sc_p += A^(CHUNK*2^l) * sc_{p-2^l} ----
    for (int l = 0; l < LEVELS; ++l) {
        int d = 1 << l;
        float t[8];
        bool act = (tid >= d);
        if (act) {
#pragma unroll
            for (int i = 0; i < 8; ++i) t[i] = S[tid - d][i];
        }
        __syncthreads();
        if (act) {
#pragma unroll
            for (int r = 0; r < 8; ++r) {
                float acc = sc[r];
#pragma unroll
                for (int c = 0; c < 8; ++c) acc = fmaf(Mats[l][r][c], t[c], acc);
                sc[r] = acc;
            }
#pragma unroll
            for (int i = 0; i < 8; ++i) S[tid][i] = sc[i];
        }
        __syncthreads();
    }

    // ---- exclusive state = inclusive of thread tid-1 (true incoming state) ----
    float init[8];
    if (tid == 0) {
#pragma unroll
        for (int i = 0; i < 8; ++i) init[i] = 0.f;
    } else {
#pragma unroll
        for (int i = 0; i < 8; ++i) init[i] = S[tid - 1][i];
    }

    // ---- Pass B: re-run chunk from correct initial state, write output ----
    float r1[K], r2[K];
#pragma unroll
    for (int k = 0; k < K; ++k) { r1[k] = init[2 * k]; r2[k] = init[2 * k + 1]; }

    float4* __restrict__ yo =
        reinterpret_cast<float4*>(yout + (size_t)ch * LSIG + (size_t)tid * CHUNK);
#pragma unroll 1
    for (int i = 0; i < CHUNK / 4; ++i) {
        float4 v = xin[i];
        float4 o;
        o.x = cascade_step(v.x, r1, r2, cf);
        o.y = cascade_step(v.y, r1, r2, cf);
        o.z = cascade_step(v.z, r1, r2, cf);
        o.w = cascade_step(v.w, r1, r2, cf);
        yo[i] = o;
    }
}

extern "C" void kernel_launch(void* const* d_in, const int* in_sizes, int n_in,
                              void* d_out, int out_size)
{
    const float* x  = (const float*)d_in[0];   // (B, C, L) float32
    const float* Bs = (const float*)d_in[1];   // (B, C, K, 3) float32
    const float* As = (const float*)d_in[2];   // (B, C, K, 3) float32
    float* y = (float*)d_out;                  // (B, C, L) float32

    iir_cascade_kernel<<<NCH, THREADS>>>(x, Bs, As, y);
}

// round 3
// speedup vs baseline: 1.1046x; 1.1046x over previous
#include <cuda_runtime.h>

#define NB 64
#define NC 2
#define LSIG 131072
#define K 4
#define NCH (NB*NC)
#define THREADS 512
#define SUB 128                 /* samples per sub-chunk (scan element) */
#define NELEM (LSIG/SUB)        /* 1024 scan elements, 2 per thread */
#define LEVELS 9                /* log2(THREADS) block scan over pair-aggregates */

typedef unsigned long long u64;

__device__ __forceinline__ u64 pk2(float lo, float hi) {
    u64 r; asm("mov.b64 %0,{%1,%2};" : "=l"(r) : "f"(lo), "f"(hi)); return r;
}
__device__ __forceinline__ void upk2(u64 v, float& lo, float& hi) {
    asm("mov.b64 {%0,%1},%2;" : "=f"(lo), "=f"(hi) : "l"(v));
}
__device__ __forceinline__ u64 fma2(u64 a, u64 b, u64 c) {
    u64 d; asm("fma.rn.f32x2 %0,%1,%2,%3;" : "=l"(d) : "l"(a), "l"(b), "l"(c)); return d;
}
__device__ __forceinline__ u64 mul2(u64 a, u64 b) {
    u64 d; asm("mul.rn.f32x2 %0,%1,%2;" : "=l"(d) : "l"(a), "l"(b)); return d;
}

struct Coef { float b0[K], b1[K], b2[K], na1[K], na2[K]; };
struct Coef2 { u64 b0[K], b1[K], b2[K], na1[K], na2[K]; };

// scalar step (used only for building the 8x8 state matrix A)
__device__ __forceinline__ float cascade_step(float u, float s1[K], float s2[K], const Coef& cf) {
#pragma unroll
    for (int k = 0; k < K; ++k) {
        float y = fmaf(cf.b0[k], u, s1[k]);
        s1[k] = fmaf(cf.b1[k], u, fmaf(cf.na1[k], y, s2[k]));
        s2[k] = fmaf(cf.b2[k], u, cf.na2[k] * y);
        u = y;
    }
    return u;
}

// packed step: two independent signal streams in the f32x2 lanes
__device__ __forceinline__ u64 cascade_step2(u64 u, u64 s1[K], u64 s2[K], const Coef2& cf) {
#pragma unroll
    for (int k = 0; k < K; ++k) {
        u64 y = fma2(cf.b0[k], u, s1[k]);
        s1[k] = fma2(cf.b1[k], u, fma2(cf.na1[k], y, s2[k]));
        s2[k] = fma2(cf.b2[k], u, mul2(cf.na2[k], y));
        u = y;
    }
    return u;
}

__global__ void __launch_bounds__(THREADS, 1)
iir_cascade_kernel(const float* __restrict__ x,
                   const float* __restrict__ Bs,
                   const float* __restrict__ As,
                   float* __restrict__ yout)
{
    __shared__ float S[THREADS][8];         // pair-aggregate scan array
    __shared__ float Mats[LEVELS][8][8];    // A^(256 * 2^l), l=0..8
    __shared__ float A128[8][8];            // A^128 (pair combine)
    __shared__ float P[8][8];               // running power of A

    const int ch  = blockIdx.x;
    const int tid = threadIdx.x;

    // ---- load + normalize coefficients ----
    Coef cf;
    {
        const float* bs = Bs + (size_t)ch * K * 3;
        const float* as = As + (size_t)ch * K * 3;
#pragma unroll
        for (int k = 0; k < K; ++k) {
            float inv = 1.0f / as[k * 3 + 0];
            cf.b0[k]  = bs[k * 3 + 0] * inv;
            cf.b1[k]  = bs[k * 3 + 1] * inv;
            cf.b2[k]  = bs[k * 3 + 2] * inv;
            cf.na1[k] = -(as[k * 3 + 1] * inv);
            cf.na2[k] = -(as[k * 3 + 2] * inv);
        }
    }

    // ---- build state matrix A (column i = one zero-input step from e_i) ----
    if (tid < 8) {
        float t1[K], t2[K];
#pragma unroll
        for (int k = 0; k < K; ++k) {
            t1[k] = (2 * k     == tid) ? 1.f : 0.f;
            t2[k] = (2 * k + 1 == tid) ? 1.f : 0.f;
        }
        cascade_step(0.f, t1, t2, cf);
#pragma unroll
        for (int k = 0; k < K; ++k) {
            P[2 * k][tid]     = t1[k];
            P[2 * k + 1][tid] = t2[k];
        }
    }

    // ---- broadcast-pack coefficients for f32x2 ----
    Coef2 c2;
#pragma unroll
    for (int k = 0; k < K; ++k) {
        c2.b0[k]  = pk2(cf.b0[k],  cf.b0[k]);
        c2.b1[k]  = pk2(cf.b1[k],  cf.b1[k]);
        c2.b2[k]  = pk2(cf.b2[k],  cf.b2[k]);
        c2.na1[k] = pk2(cf.na1[k], cf.na1[k]);
        c2.na2[k] = pk2(cf.na2[k], cf.na2[k]);
    }

    // thread tid owns chunks 2*tid (lane0, samples [tid*256, +128)) and
    // 2*tid+1 (lane1, samples [tid*256+128, +256))
    const float* base = x + (size_t)ch * LSIG + (size_t)tid * (2 * SUB);
    const float4* __restrict__ xlo = reinterpret_cast<const float4*>(base);
    const float4* __restrict__ xhi = reinterpret_cast<const float4*>(base + SUB);

    // ---- Pass A: zero-init packed run over both sub-chunks ----
    u64 s1[K] = {0, 0, 0, 0};
    u64 s2[K] = {0, 0, 0, 0};
#pragma unroll 1
    for (int i = 0; i < SUB / 4; ++i) {
        float4 a = xlo[i];
        float4 b = xhi[i];
        cascade_step2(pk2(a.x, b.x), s1, s2, c2);
        cascade_step2(pk2(a.y, b.y), s1, s2, c2);
        cascade_step2(pk2(a.z, b.z), s1, s2, c2);
        cascade_step2(pk2(a.w, b.w), s1, s2, c2);
    }
    float sc_lo[8], sc_hi[8];
#pragma unroll
    for (int k = 0; k < K; ++k) {
        upk2(s1[k], sc_lo[2 * k],     sc_hi[2 * k]);
        upk2(s2[k], sc_lo[2 * k + 1], sc_hi[2 * k + 1]);
    }

    __syncthreads();   // P (matrix A) visible to squaring warps

    // ---- repeated squaring by warps 0-1 only: after it, P = A^(2^it).
    //      A128 = A^(2^7); Mats[it-8] = A^(2^it) for it=8..16 ----
    if (tid < 64) {
        const int r = tid >> 3, c = tid & 7;
        for (int it = 1; it <= 16; ++it) {
            float val = 0.f;
#pragma unroll
            for (int kk = 0; kk < 8; ++kk) val = fmaf(P[r][kk], P[kk][c], val);
            asm volatile("bar.sync 1, 64;" ::: "memory");
            P[r][c] = val;
            if (it == 7) A128[r][c] = val;
            if (it >= 8) Mats[it - 8][r][c] = val;
            asm volatile("bar.sync 1, 64;" ::: "memory");
        }
    }
    __syncthreads();   // A128 / Mats visible to all

    // ---- local pair combine: agg = A128 * sc_lo + sc_hi ----
    float agg[8];
#pragma unroll
    for (int r = 0; r < 8; ++r) {
        float acc = sc_hi[r];
#pragma unroll
        for (int c = 0; c < 8; ++c) acc = fmaf(A128[r][c], sc_lo[c], acc);
        agg[r] = acc;
        S[tid][r] = acc;
    }
    __syncthreads();

    // ---- Kogge-Stone affine scan over 512 pair-aggregates ----
    for (int l = 0; l < LEVELS; ++l) {
        int d = 1 << l;
        float t[8];
        bool act = (tid >= d);
        if (act) {
#pragma unroll
            for (int i = 0; i < 8; ++i) t[i] = S[tid - d][i];
        }
        __syncthreads();
        if (act) {
#pragma unroll
            for (int r = 0; r < 8; ++r) {
                float acc = agg[r];
#pragma unroll
                for (int c = 0; c < 8; ++c) acc = fmaf(Mats[l][r][c], t[c], acc);
                agg[r] = acc;
            }
#pragma unroll
            for (int i = 0; i < 8; ++i) S[tid][i] = agg[i];
        }
        __syncthreads();
    }

    // ---- initial states: lane0 = inclusive of previous pair; lane1 = A128*init0 + sc_lo ----
    float init0[8], init1[8];
    if (tid == 0) {
#pragma unroll
        for (int i = 0; i < 8; ++i) init0[i] = 0.f;
    } else {
#pragma unroll
        for (int i = 0; i < 8; ++i) init0[i] = S[tid - 1][i];
    }
#pragma unroll
    for (int r = 0; r < 8; ++r) {
        float acc = sc_lo[r];
#pragma unroll
        for (int c = 0; c < 8; ++c) acc = fmaf(A128[r][c], init0[c], acc);
        init1[r] = acc;
    }

    // ---- Pass B: packed rerun from corrected states, write outputs ----
    u64 r1[K], r2[K];
#pragma unroll
    for (int k = 0; k < K; ++k) {
        r1[k] = pk2(init0[2 * k],     init1[2 * k]);
        r2[k] = pk2(init0[2 * k + 1], init1[2 * k + 1]);
    }

    float* obase = yout + (size_t)ch * LSIG + (size_t)tid * (2 * SUB);
    float4* __restrict__ ylo = reinterpret_cast<float4*>(obase);
    float4* __restrict__ yhi = reinterpret_cast<float4*>(obase + SUB);
#pragma unroll 1
    for (int i = 0; i < SUB / 4; ++i) {
        float4 a = xlo[i];
        float4 b = xhi[i];
        float4 olo, ohi;
        u64 y0 = cascade_step2(pk2(a.x, b.x), r1, r2, c2);
        u64 y1 = cascade_step2(pk2(a.y, b.y), r1, r2, c2);
        u64 y2 = cascade_step2(pk2(a.z, b.z), r1, r2, c2);
        u64 y3 = cascade_step2(pk2(a.w, b.w), r1, r2, c2);
        upk2(y0, olo.x, ohi.x);
        upk2(y1, olo.y, ohi.y);
        upk2(y2, olo.z, ohi.z);
        upk2(y3, olo.w, ohi.w);
        ylo[i] = olo;
        yhi[i] = ohi;
    }
}

extern "C" void kernel_launch(void* const* d_in, const int* in_sizes, int n_in,
                              void* d_out, int out_size)
{
    const float* x  = (const float*)d_in[0];   // (B, C, L) float32
    const float* Bs = (const float*)d_in[1];   // (B, C, K, 3) float32
    const float* As = (const float*)d_in[2];   // (B, C, K, 3) float32
    float* y = (float*)d_out;                  // (B, C, L) float32

    iir_cascade_kernel<<<NCH, THREADS>>>(x, Bs, As, y);
}

// round 6
// speedup vs baseline: 1.1986x; 1.0851x over previous
#include <cuda_runtime.h>

#define NB 64
#define NC 2
#define LSIG 131072
#define K 4
#define NCH (NB*NC)
#define THREADS 512
#define SUB 128                 /* samples per chunk (scan element) */
#define LEVELS 9                /* log2(THREADS) block scan over pair-aggregates */
#define TILE 32                 /* samples per smem tile */
#define NTILES (SUB/TILE)       /* 4 */
#define PITCH 33                /* smem row pitch (odd -> conflict-free reads) */

typedef unsigned long long u64;

__device__ __forceinline__ u64 pk2(float lo, float hi) {
    u64 r; asm("mov.b64 %0,{%1,%2};" : "=l"(r) : "f"(lo), "f"(hi)); return r;
}
__device__ __forceinline__ void upk2(u64 v, float& lo, float& hi) {
    asm("mov.b64 {%0,%1},%2;" : "=f"(lo), "=f"(hi) : "l"(v));
}
__device__ __forceinline__ u64 fma2(u64 a, u64 b, u64 c) {
    u64 d; asm("fma.rn.f32x2 %0,%1,%2,%3;" : "=l"(d) : "l"(a), "l"(b), "l"(c)); return d;
}
__device__ __forceinline__ u64 mul2(u64 a, u64 b) {
    u64 d; asm("mul.rn.f32x2 %0,%1,%2;" : "=l"(d) : "l"(a), "l"(b)); return d;
}

struct Coef { float b0[K], b1[K], b2[K], na1[K], na2[K]; };
struct Coef2 { u64 b0[K], b1[K], b2[K], na1[K], na2[K]; };

// scalar step (only to build the 8x8 state matrix A)
__device__ __forceinline__ float cascade_step(float u, float s1[K], float s2[K], const Coef& cf) {
#pragma unroll
    for (int k = 0; k < K; ++k) {
        float y = fmaf(cf.b0[k], u, s1[k]);
        s1[k] = fmaf(cf.b1[k], u, fmaf(cf.na1[k], y, s2[k]));
        s2[k] = fmaf(cf.b2[k], u, cf.na2[k] * y);
        u = y;
    }
    return u;
}

// packed step: two independent signal streams in the f32x2 lanes
__device__ __forceinline__ u64 cascade_step2(u64 u, u64 s1[K], u64 s2[K], const Coef2& cf) {
#pragma unroll
    for (int k = 0; k < K; ++k) {
        u64 y = fma2(cf.b0[k], u, s1[k]);
        s1[k] = fma2(cf.b1[k], u, fma2(cf.na1[k], y, s2[k]));
        s2[k] = fma2(cf.b2[k], u, mul2(cf.na2[k], y));
        u = y;
    }
    return u;
}

extern __shared__ float dyn_smem[];   // Lo[512][PITCH] then Hi[512][PITCH]

__global__ void __launch_bounds__(THREADS, 1)
iir_cascade_kernel(const float* __restrict__ x,
                   const float* __restrict__ Bs,
                   const float* __restrict__ As,
                   float* __restrict__ yout)
{
    __shared__ float S[THREADS][8];         // pair-aggregate scan array
    __shared__ float Mats[LEVELS][8][8];    // A^(256 * 2^l), l=0..8
    __shared__ float A128[8][8];            // A^128 (pair combine)
    __shared__ float P[8][8];               // running power of A

    float* __restrict__ Lo = dyn_smem;
    float* __restrict__ Hi = dyn_smem + THREADS * PITCH;

    const int ch  = blockIdx.x;
    const int tid = threadIdx.x;

    // ---- load + normalize coefficients ----
    Coef cf;
    {
        const float* bs = Bs + (size_t)ch * K * 3;
        const float* as = As + (size_t)ch * K * 3;
#pragma unroll
        for (int k = 0; k < K; ++k) {
            float inv = 1.0f / as[k * 3 + 0];
            cf.b0[k]  = bs[k * 3 + 0] * inv;
            cf.b1[k]  = bs[k * 3 + 1] * inv;
            cf.b2[k]  = bs[k * 3 + 2] * inv;
            cf.na1[k] = -(as[k * 3 + 1] * inv);
            cf.na2[k] = -(as[k * 3 + 2] * inv);
        }
    }

    // ---- build state matrix A (column i = one zero-input step from e_i) ----
    if (tid < 8) {
        float t1[K], t2[K];
#pragma unroll
        for (int k = 0; k < K; ++k) {
            t1[k] = (2 * k     == tid) ? 1.f : 0.f;
            t2[k] = (2 * k + 1 == tid) ? 1.f : 0.f;
        }
        cascade_step(0.f, t1, t2, cf);
#pragma unroll
        for (int k = 0; k < K; ++k) {
            P[2 * k][tid]     = t1[k];
            P[2 * k + 1][tid] = t2[k];
        }
    }

    // ---- broadcast-pack coefficients for f32x2 ----
    Coef2 c2;
#pragma unroll
    for (int k = 0; k < K; ++k) {
        c2.b0[k]  = pk2(cf.b0[k],  cf.b0[k]);
        c2.b1[k]  = pk2(cf.b1[k],  cf.b1[k]);
        c2.b2[k]  = pk2(cf.b2[k],  cf.b2[k]);
        c2.na1[k] = pk2(cf.na1[k], cf.na1[k]);
        c2.na2[k] = pk2(cf.na2[k], cf.na2[k]);
    }

    const float* __restrict__ xch = x + (size_t)ch * LSIG;
    float* __restrict__ ych = yout + (size_t)ch * LSIG;

    // ================= Pass A: zero-init packed run, smem-staged tiles ========
    u64 s1[K] = {0, 0, 0, 0};
    u64 s2[K] = {0, 0, 0, 0};
    {
        const float* lrow = Lo + tid * PITCH;
        const float* hrow = Hi + tid * PITCH;
#pragma unroll 1
        for (int tile = 0; tile < NTILES; ++tile) {
            const int t0 = tile * TILE;
            __syncthreads();   // previous tile's reads done before overwrite
            // coalesced tile load: 1024 chunks x 8 float4
#pragma unroll
            for (int it = 0; it < 16; ++it) {
                int f = tid + it * THREADS;          // 0..8191
                int c = f >> 3, w = f & 7;
                float4 v = *reinterpret_cast<const float4*>(xch + (size_t)c * SUB + t0 + w * 4);
                float* row = ((c & 1) ? Hi : Lo) + (c >> 1) * PITCH + w * 4;
                row[0] = v.x; row[1] = v.y; row[2] = v.z; row[3] = v.w;
            }
            __syncthreads();
#pragma unroll 4
            for (int j = 0; j < TILE; ++j) {
                cascade_step2(pk2(lrow[j], hrow[j]), s1, s2, c2);
            }
        }
    }
    float sc_lo[8], sc_hi[8];
#pragma unroll
    for (int k = 0; k < K; ++k) {
        upk2(s1[k], sc_lo[2 * k],     sc_hi[2 * k]);
        upk2(s2[k], sc_lo[2 * k + 1], sc_hi[2 * k + 1]);
    }

    __syncthreads();   // P (matrix A) visible; pass-A smem traffic done

    // ---- repeated squaring by warps 0-1: after it, P = A^(2^it).
    //      A128 = A^(2^7); Mats[it-8] = A^(2^it) for it=8..16 ----
    if (tid < 64) {
        const int r = tid >> 3, c = tid & 7;
        for (int it = 1; it <= 16; ++it) {
            float val = 0.f;
#pragma unroll
            for (int kk = 0; kk < 8; ++kk) val = fmaf(P[r][kk], P[kk][c], val);
            asm volatile("bar.sync 1, 64;" ::: "memory");
            P[r][c] = val;
            if (it == 7) A128[r][c] = val;
            if (it >= 8) Mats[it - 8][r][c] = val;
            asm volatile("bar.sync 1, 64;" ::: "memory");
        }
    }
    __syncthreads();   // A128 / Mats visible to all

    // ---- local pair combine: agg = A128 * sc_lo + sc_hi ----
    float agg[8];
#pragma unroll
    for (int r = 0; r < 8; ++r) {
        float acc = sc_hi[r];
#pragma unroll
        for (int c = 0; c < 8; ++c) acc = fmaf(A128[r][c], sc_lo[c], acc);
        agg[r] = acc;
        S[tid][r] = acc;
    }
    __syncthreads();

    // ---- Kogge-Stone affine scan over 512 pair-aggregates ----
    for (int l = 0; l < LEVELS; ++l) {
        int d = 1 << l;
        float t[8];
        bool act = (tid >= d);
        if (act) {
#pragma unroll
            for (int i = 0; i < 8; ++i) t[i] = S[tid - d][i];
        }
        __syncthreads();
        if (act) {
#pragma unroll
            for (int r = 0; r < 8; ++r) {
                float acc = agg[r];
#pragma unroll
                for (int c = 0; c < 8; ++c) acc = fmaf(Mats[l][r][c], t[c], acc);
                agg[r] = acc;
            }
#pragma unroll
            for (int i = 0; i < 8; ++i) S[tid][i] = agg[i];
        }
        __syncthreads();
    }

    // ---- initial states: lane0 = inclusive of previous pair; lane1 = A128*init0 + sc_lo ----
    float init0[8], init1[8];
    if (tid == 0) {
#pragma unroll
        for (int i = 0; i < 8; ++i) init0[i] = 0.f;
    } else {
#pragma unroll
        for (int i = 0; i < 8; ++i) init0[i] = S[tid - 1][i];
    }
#pragma unroll
    for (int r = 0; r < 8; ++r) {
        float acc = sc_lo[r];
#pragma unroll
        for (int c = 0; c < 8; ++c) acc = fmaf(A128[r][c], init0[c], acc);
        init1[r] = acc;
    }

    // ================= Pass B: rerun from corrected states, staged I/O ========
    u64 r1[K], r2[K];
#pragma unroll
    for (int k = 0; k < K; ++k) {
        r1[k] = pk2(init0[2 * k],     init1[2 * k]);
        r2[k] = pk2(init0[2 * k + 1], init1[2 * k + 1]);
    }

    {
        float* lrow = Lo + tid * PITCH;
        float* hrow = Hi + tid * PITCH;
#pragma unroll 1
        for (int tile = 0; tile < NTILES; ++tile) {
            const int t0 = tile * TILE;
            __syncthreads();   // previous tile's store-out done before overwrite
#pragma unroll
            for (int it = 0; it < 16; ++it) {
                int f = tid + it * THREADS;
                int c = f >> 3, w = f & 7;
                float4 v = *reinterpret_cast<const float4*>(xch + (size_t)c * SUB + t0 + w * 4);
                float* row = ((c & 1) ? Hi : Lo) + (c >> 1) * PITCH + w * 4;
                row[0] = v.x; row[1] = v.y; row[2] = v.z; row[3] = v.w;
            }
            __syncthreads();
            // compute, overwrite own rows in place with outputs
#pragma unroll 4
            for (int j = 0; j < TILE; ++j) {
                u64 y = cascade_step2(pk2(lrow[j], hrow[j]), r1, r2, c2);
                upk2(y, lrow[j], hrow[j]);
            }
            __syncthreads();
            // coalesced store-out (inverse mapping)
#pragma unroll
            for (int it = 0; it < 16; ++it) {
                int f = tid + it * THREADS;
                int c = f >> 3, w = f & 7;
                const float* row = ((c & 1) ? Hi : Lo) + (c >> 1) * PITCH + w * 4;
                float4 v;
                v.x = row[0]; v.y = row[1]; v.z = row[2]; v.w = row[3];
                *reinterpret_cast<float4*>(ych + (size_t)c * SUB + t0 + w * 4) = v;
            }
        }
    }
}

extern "C" void kernel_launch(void* const* d_in, const int* in_sizes, int n_in,
                              void* d_out, int out_size)
{
    const float* x  = (const float*)d_in[0];   // (B, C, L) float32
    const float* Bs = (const float*)d_in[1];   // (B, C, K, 3) float32
    const float* As = (const float*)d_in[2];   // (B, C, K, 3) float32
    float* y = (float*)d_out;                  // (B, C, L) float32

    const int dyn_bytes = 2 * THREADS * PITCH * sizeof(float);   // 135168
    static bool attr_set = false;
    if (!attr_set) {
        cudaFuncSetAttribute(iir_cascade_kernel,
                             cudaFuncAttributeMaxDynamicSharedMemorySize, dyn_bytes);
        attr_set = true;
    }
    iir_cascade_kernel<<<NCH, THREADS, dyn_bytes>>>(x, Bs, As, y);
}